// round 3
// baseline (speedup 1.0000x reference)
#include <cuda_runtime.h>
#include <cstdint>

// Problem constants
static constexpr int B = 32;
static constexpr int L = 4096;
static constexpr int C = 8;
static constexpr int T = 64;
static constexpr long long NELEM = (long long)B * L * C;   // 1,048,576

static constexpr int RED_BLOCKS  = 256;
static constexpr int RED_THREADS = 256;
// 256*256 threads * 16 elems = 1,048,576 == NELEM exactly

// Deterministic scratch (fixed-slot partials, no atomics)
__device__ float g_psum[RED_BLOCKS];
__device__ float g_psumsq[RED_BLOCKS];

__device__ __forceinline__ float rsqrt_approx(float x) {
    float r;
    asm("rsqrt.approx.f32 %0, %1;" : "=f"(r) : "f"(x));
    return r;
}

// ---------------------------------------------------------------------------
// K1: per-block partial sums of delta and delta^2, fully vectorized.
// Each thread owns 16 contiguous elements [base, base+16) and loads the
// covering window [base-8, base+16) as 6 independent float4s (MLP=6).
// a[k] = in[base-8+k]; delta(idx=base+j) = a[j+8] - a[j]; forced 0 at l==0
// (which happens iff base % (L*C) == 0 and j < 8, since 16 | L*C).
// ---------------------------------------------------------------------------
__global__ void __launch_bounds__(RED_THREADS) reduce_kernel(const float* __restrict__ in) {
    const int tid  = blockIdx.x * blockDim.x + threadIdx.x;
    const int base = tid * 16;
    const float* p = in + base;

    float4 v0, v1, v2, v3, v4, v5;
    v2 = *reinterpret_cast<const float4*>(p);
    v3 = *reinterpret_cast<const float4*>(p + 4);
    v4 = *reinterpret_cast<const float4*>(p + 8);
    v5 = *reinterpret_cast<const float4*>(p + 12);
    if (base == 0) {
        v0 = make_float4(0.f, 0.f, 0.f, 0.f);
        v1 = v0;
    } else {
        v0 = *reinterpret_cast<const float4*>(p - 8);
        v1 = *reinterpret_cast<const float4*>(p - 4);
    }

    float a[24] = { v0.x, v0.y, v0.z, v0.w,  v1.x, v1.y, v1.z, v1.w,
                    v2.x, v2.y, v2.z, v2.w,  v3.x, v3.y, v3.z, v3.w,
                    v4.x, v4.y, v4.z, v4.w,  v5.x, v5.y, v5.z, v5.w };

    const bool head = (base & (L * C - 1)) == 0;   // first 16-chunk of a batch row
    float s = 0.0f, q = 0.0f;
    #pragma unroll
    for (int j = 0; j < 16; ++j) {
        float delta = a[j + 8] - a[j];
        if (head && j < 8) delta = 0.0f;
        s += delta;
        q  = fmaf(delta, delta, q);
    }

    __shared__ float sh_s[RED_THREADS];
    __shared__ float sh_q[RED_THREADS];
    int t = threadIdx.x;
    sh_s[t] = s;
    sh_q[t] = q;
    __syncthreads();
    #pragma unroll
    for (int o = RED_THREADS / 2; o > 0; o >>= 1) {
        if (t < o) { sh_s[t] += sh_s[t + o]; sh_q[t] += sh_q[t + o]; }
        __syncthreads();
    }
    if (t == 0) {
        g_psum[blockIdx.x]   = sh_s[0];
        g_psumsq[blockIdx.x] = sh_q[0];
    }
}

// ---------------------------------------------------------------------------
// K2 (fused into K3): every lif block reduces the 256 partials itself
// (1KB, L2-broadcast across blocks) -> no separate finalize launch.
//
// K3: normalize delta, encode across T=64, LIF recurrence, spike out.
// One thread = 8 l's for one (b, c) as two disjoint 4-chunks (lA, lA+L/2):
// every float4 store instruction is a full warp-contiguous 512B burst.
// Streaming stores (.cs): output is never re-read.
// out layout: [B, T, C, L] -> ((b*T + t)*C + c)*L + l
// ---------------------------------------------------------------------------
__global__ void __launch_bounds__(256) lif_kernel(
    const float* __restrict__ in,
    const float* __restrict__ enc_w,
    const float* __restrict__ enc_b,
    const float* __restrict__ bn_gamma,
    const float* __restrict__ bn_beta,
    float* __restrict__ out)
{
    __shared__ float sw[T];
    __shared__ float sb[T];
    __shared__ float sh_s[RED_BLOCKS];
    __shared__ float sh_q[RED_BLOCKS];
    __shared__ float s_mean, s_inv;

    const int t = threadIdx.x;
    if (t < T) {
        sw[t] = enc_w[t];   // enc_w is [T,1]
        sb[t] = enc_b[t];
    }
    sh_s[t] = g_psum[t];
    sh_q[t] = g_psumsq[t];
    __syncthreads();
    #pragma unroll
    for (int o = RED_BLOCKS / 2; o > 0; o >>= 1) {
        if (t < o) { sh_s[t] += sh_s[t + o]; sh_q[t] += sh_q[t + o]; }
        __syncthreads();
    }
    if (t == 0) {
        const float invN = 1.0f / (float)NELEM;
        float mean = sh_s[0] * invN;
        float var  = fmaf(-mean, mean, sh_q[0] * invN);
        s_mean = mean;
        s_inv  = rsqrt_approx(var + 1e-5f);
    }
    __syncthreads();

    const int idx = blockIdx.x * blockDim.x + threadIdx.x;  // 0 .. 131071
    const int lv  = idx & ((L / 8) - 1);        // 0..511
    const int c   = (idx >> 9) & (C - 1);
    const int b   = idx >> 12;
    const int lA  = lv * 4;                     // chunk A: [lA, lA+4)
    const int lB  = lA + (L / 2);               // chunk B: [lB, lB+4)

    const float mean = s_mean;
    const float inv  = s_inv;
    const float ga   = bn_gamma[0];
    const float be   = bn_beta[0];

    const float* inp = in + ((long long)b * L) * C + c;

    float dA[4], dB[4];
    #pragma unroll
    for (int j = 0; j < 4; ++j) {
        int la = lA + j;
        float deltaA = (la == 0) ? 0.0f : (inp[la * C] - inp[(la - 1) * C]);
        float xa = (deltaA - mean) * inv;
        dA[j] = xa * ga + be;

        int lb = lB + j;
        float deltaB = inp[lb * C] - inp[(lb - 1) * C];   // lB >= 2048, never 0
        float xb = (deltaB - mean) * inv;
        dB[j] = xb * ga + be;
    }

    float vA0 = 0.f, vA1 = 0.f, vA2 = 0.f, vA3 = 0.f;
    float vB0 = 0.f, vB1 = 0.f, vB2 = 0.f, vB3 = 0.f;

    float* opA = out + (((long long)b * T) * C + c) * L + lA;
    float* opB = opA + (L / 2);

    #pragma unroll 8
    for (int tt = 0; tt < T; ++tt) {
        const float w  = sw[tt];
        const float bb = sb[tt];
        const long long off = (long long)tt * (C * L);
        float4 sa, sbv;

        float x;
        x = fmaf(dA[0], w, bb); vA0 = vA0 + (x - vA0) * 0.5f;
        bool p0 = (vA0 >= 1.0f); sa.x = p0 ? 1.0f : 0.0f; vA0 = p0 ? 0.0f : vA0;
        x = fmaf(dA[1], w, bb); vA1 = vA1 + (x - vA1) * 0.5f;
        bool p1 = (vA1 >= 1.0f); sa.y = p1 ? 1.0f : 0.0f; vA1 = p1 ? 0.0f : vA1;
        x = fmaf(dA[2], w, bb); vA2 = vA2 + (x - vA2) * 0.5f;
        bool p2 = (vA2 >= 1.0f); sa.z = p2 ? 1.0f : 0.0f; vA2 = p2 ? 0.0f : vA2;
        x = fmaf(dA[3], w, bb); vA3 = vA3 + (x - vA3) * 0.5f;
        bool p3 = (vA3 >= 1.0f); sa.w = p3 ? 1.0f : 0.0f; vA3 = p3 ? 0.0f : vA3;

        x = fmaf(dB[0], w, bb); vB0 = vB0 + (x - vB0) * 0.5f;
        bool q0 = (vB0 >= 1.0f); sbv.x = q0 ? 1.0f : 0.0f; vB0 = q0 ? 0.0f : vB0;
        x = fmaf(dB[1], w, bb); vB1 = vB1 + (x - vB1) * 0.5f;
        bool q1 = (vB1 >= 1.0f); sbv.y = q1 ? 1.0f : 0.0f; vB1 = q1 ? 0.0f : vB1;
        x = fmaf(dB[2], w, bb); vB2 = vB2 + (x - vB2) * 0.5f;
        bool q2 = (vB2 >= 1.0f); sbv.z = q2 ? 1.0f : 0.0f; vB2 = q2 ? 0.0f : vB2;
        x = fmaf(dB[3], w, bb); vB3 = vB3 + (x - vB3) * 0.5f;
        bool q3 = (vB3 >= 1.0f); sbv.w = q3 ? 1.0f : 0.0f; vB3 = q3 ? 0.0f : vB3;

        __stcs(reinterpret_cast<float4*>(opA + off), sa);
        __stcs(reinterpret_cast<float4*>(opB + off), sbv);
    }
}

// ---------------------------------------------------------------------------
extern "C" void kernel_launch(void* const* d_in, const int* in_sizes, int n_in,
                              void* d_out, int out_size)
{
    const float* in       = (const float*)d_in[0];
    const float* bn_gamma = (const float*)d_in[1];
    const float* bn_beta  = (const float*)d_in[2];
    const float* enc_w    = (const float*)d_in[3];
    const float* enc_b    = (const float*)d_in[4];
    float* out            = (float*)d_out;

    reduce_kernel<<<RED_BLOCKS, RED_THREADS>>>(in);

    const int total_thr = B * C * (L / 8);      // 131072
    lif_kernel<<<total_thr / 256, 256>>>(in, enc_w, enc_b, bn_gamma, bn_beta, out);
}

// round 4
// speedup vs baseline: 1.3839x; 1.3839x over previous
#include <cuda_runtime.h>
#include <cstdint>

// Problem constants
static constexpr int B = 32;
static constexpr int L = 4096;
static constexpr int C = 8;
static constexpr int T = 64;
static constexpr long long NELEM = (long long)B * L * C;   // 1,048,576

static constexpr int RED_BLOCKS  = 256;
static constexpr int RED_THREADS = 256;
// 256*256 threads * 16 elems = 1,048,576 == NELEM exactly

// Deterministic scratch (fixed-slot partials, no atomics)
__device__ float g_psum[RED_BLOCKS];
__device__ float g_psumsq[RED_BLOCKS];
__device__ float g_mean;
__device__ float g_inv;   // rsqrt.approx(var + eps)

__device__ __forceinline__ float rsqrt_approx(float x) {
    float r;
    asm("rsqrt.approx.f32 %0, %1;" : "=f"(r) : "f"(x));
    return r;
}

// ---------------------------------------------------------------------------
// K1: per-block partial sums of delta and delta^2, fully vectorized.
// Each thread owns 16 contiguous elements [base, base+16) and loads the
// covering window [base-8, base+16) as 6 independent float4s (MLP=6).
// delta(idx=base+j) = a[j+8] - a[j]; forced 0 at l==0 (iff base % (L*C)==0
// and j < 8, since 16 | L*C).
// ---------------------------------------------------------------------------
__global__ void __launch_bounds__(RED_THREADS) reduce_kernel(const float* __restrict__ in) {
    const int tid  = blockIdx.x * blockDim.x + threadIdx.x;
    const int base = tid * 16;
    const float* p = in + base;

    float4 v0, v1, v2, v3, v4, v5;
    v2 = *reinterpret_cast<const float4*>(p);
    v3 = *reinterpret_cast<const float4*>(p + 4);
    v4 = *reinterpret_cast<const float4*>(p + 8);
    v5 = *reinterpret_cast<const float4*>(p + 12);
    if (base == 0) {
        v0 = make_float4(0.f, 0.f, 0.f, 0.f);
        v1 = v0;
    } else {
        v0 = *reinterpret_cast<const float4*>(p - 8);
        v1 = *reinterpret_cast<const float4*>(p - 4);
    }

    float a[24] = { v0.x, v0.y, v0.z, v0.w,  v1.x, v1.y, v1.z, v1.w,
                    v2.x, v2.y, v2.z, v2.w,  v3.x, v3.y, v3.z, v3.w,
                    v4.x, v4.y, v4.z, v4.w,  v5.x, v5.y, v5.z, v5.w };

    const bool head = (base & (L * C - 1)) == 0;   // first 16-chunk of a batch row
    float s = 0.0f, q = 0.0f;
    #pragma unroll
    for (int j = 0; j < 16; ++j) {
        float delta = a[j + 8] - a[j];
        if (head && j < 8) delta = 0.0f;
        s += delta;
        q  = fmaf(delta, delta, q);
    }

    __shared__ float sh_s[RED_THREADS];
    __shared__ float sh_q[RED_THREADS];
    int t = threadIdx.x;
    sh_s[t] = s;
    sh_q[t] = q;
    __syncthreads();
    #pragma unroll
    for (int o = RED_THREADS / 2; o > 0; o >>= 1) {
        if (t < o) { sh_s[t] += sh_s[t + o]; sh_q[t] += sh_q[t + o]; }
        __syncthreads();
    }
    if (t == 0) {
        g_psum[blockIdx.x]   = sh_s[0];
        g_psumsq[blockIdx.x] = sh_q[0];
    }
}

// ---------------------------------------------------------------------------
// K2: single-block finalize, shuffle-based (no fp64, minimal barriers).
// 256 threads: each loads one partial, warp-reduce, 8 warp results via smem.
// ---------------------------------------------------------------------------
__global__ void __launch_bounds__(256) finalize_kernel() {
    const int t = threadIdx.x;
    float s = g_psum[t];
    float q = g_psumsq[t];
    #pragma unroll
    for (int o = 16; o > 0; o >>= 1) {
        s += __shfl_down_sync(0xffffffffu, s, o);
        q += __shfl_down_sync(0xffffffffu, q, o);
    }
    __shared__ float ws[8], wq[8];
    if ((t & 31) == 0) { ws[t >> 5] = s; wq[t >> 5] = q; }
    __syncthreads();
    if (t == 0) {
        float S = 0.f, Q = 0.f;
        #pragma unroll
        for (int w = 0; w < 8; ++w) { S += ws[w]; Q += wq[w]; }
        const float invN = 1.0f / (float)NELEM;
        float mean = S * invN;
        float var  = fmaf(-mean, mean, Q * invN);
        g_mean = mean;
        g_inv  = rsqrt_approx(var + 1e-5f);
    }
}

// ---------------------------------------------------------------------------
// K3: main — normalize delta, encode across T=64, LIF recurrence, spike out.
// (R2 configuration restored verbatim: scalar g_mean/g_inv loads, no fused
// preamble — that fusion regressed lif 50 -> 74us in R3.)
// One thread = 8 l's for one (b, c) as two disjoint 4-chunks (lA, lA+L/2):
// every float4 store instruction is a full warp-contiguous 512B burst.
// Streaming stores (.cs): output is never re-read.
// out layout: [B, T, C, L] -> ((b*T + t)*C + c)*L + l
// ---------------------------------------------------------------------------
__global__ void __launch_bounds__(256) lif_kernel(
    const float* __restrict__ in,
    const float* __restrict__ enc_w,
    const float* __restrict__ enc_b,
    const float* __restrict__ bn_gamma,
    const float* __restrict__ bn_beta,
    float* __restrict__ out)
{
    __shared__ float sw[T];
    __shared__ float sb[T];
    if (threadIdx.x < T) {
        sw[threadIdx.x] = enc_w[threadIdx.x];   // enc_w is [T,1]
        sb[threadIdx.x] = enc_b[threadIdx.x];
    }
    __syncthreads();

    const int idx = blockIdx.x * blockDim.x + threadIdx.x;  // 0 .. 131071
    const int lv  = idx & ((L / 8) - 1);        // 0..511
    const int c   = (idx >> 9) & (C - 1);
    const int b   = idx >> 12;
    const int lA  = lv * 4;                     // chunk A: [lA, lA+4)
    const int lB  = lA + (L / 2);               // chunk B: [lB, lB+4)

    const float mean = g_mean;
    const float inv  = g_inv;
    const float ga   = bn_gamma[0];
    const float be   = bn_beta[0];

    const float* inp = in + ((long long)b * L) * C + c;

    float dA[4], dB[4];
    #pragma unroll
    for (int j = 0; j < 4; ++j) {
        int la = lA + j;
        float deltaA = (la == 0) ? 0.0f : (inp[la * C] - inp[(la - 1) * C]);
        float xa = (deltaA - mean) * inv;
        dA[j] = xa * ga + be;

        int lb = lB + j;
        float deltaB = inp[lb * C] - inp[(lb - 1) * C];   // lB >= 2048, never 0
        float xb = (deltaB - mean) * inv;
        dB[j] = xb * ga + be;
    }

    float vA0 = 0.f, vA1 = 0.f, vA2 = 0.f, vA3 = 0.f;
    float vB0 = 0.f, vB1 = 0.f, vB2 = 0.f, vB3 = 0.f;

    float* opA = out + (((long long)b * T) * C + c) * L + lA;
    float* opB = opA + (L / 2);

    #pragma unroll 8
    for (int t = 0; t < T; ++t) {
        const float w  = sw[t];
        const float bb = sb[t];
        const long long off = (long long)t * (C * L);
        float4 sa, sbv;

        float x;
        x = fmaf(dA[0], w, bb); vA0 = vA0 + (x - vA0) * 0.5f;
        bool p0 = (vA0 >= 1.0f); sa.x = p0 ? 1.0f : 0.0f; vA0 = p0 ? 0.0f : vA0;
        x = fmaf(dA[1], w, bb); vA1 = vA1 + (x - vA1) * 0.5f;
        bool p1 = (vA1 >= 1.0f); sa.y = p1 ? 1.0f : 0.0f; vA1 = p1 ? 0.0f : vA1;
        x = fmaf(dA[2], w, bb); vA2 = vA2 + (x - vA2) * 0.5f;
        bool p2 = (vA2 >= 1.0f); sa.z = p2 ? 1.0f : 0.0f; vA2 = p2 ? 0.0f : vA2;
        x = fmaf(dA[3], w, bb); vA3 = vA3 + (x - vA3) * 0.5f;
        bool p3 = (vA3 >= 1.0f); sa.w = p3 ? 1.0f : 0.0f; vA3 = p3 ? 0.0f : vA3;

        x = fmaf(dB[0], w, bb); vB0 = vB0 + (x - vB0) * 0.5f;
        bool q0 = (vB0 >= 1.0f); sbv.x = q0 ? 1.0f : 0.0f; vB0 = q0 ? 0.0f : vB0;
        x = fmaf(dB[1], w, bb); vB1 = vB1 + (x - vB1) * 0.5f;
        bool q1 = (vB1 >= 1.0f); sbv.y = q1 ? 1.0f : 0.0f; vB1 = q1 ? 0.0f : vB1;
        x = fmaf(dB[2], w, bb); vB2 = vB2 + (x - vB2) * 0.5f;
        bool q2 = (vB2 >= 1.0f); sbv.z = q2 ? 1.0f : 0.0f; vB2 = q2 ? 0.0f : vB2;
        x = fmaf(dB[3], w, bb); vB3 = vB3 + (x - vB3) * 0.5f;
        bool q3 = (vB3 >= 1.0f); sbv.w = q3 ? 1.0f : 0.0f; vB3 = q3 ? 0.0f : vB3;

        __stcs(reinterpret_cast<float4*>(opA + off), sa);
        __stcs(reinterpret_cast<float4*>(opB + off), sbv);
    }
}

// ---------------------------------------------------------------------------
extern "C" void kernel_launch(void* const* d_in, const int* in_sizes, int n_in,
                              void* d_out, int out_size)
{
    const float* in       = (const float*)d_in[0];
    const float* bn_gamma = (const float*)d_in[1];
    const float* bn_beta  = (const float*)d_in[2];
    const float* enc_w    = (const float*)d_in[3];
    const float* enc_b    = (const float*)d_in[4];
    float* out            = (float*)d_out;

    reduce_kernel<<<RED_BLOCKS, RED_THREADS>>>(in);
    finalize_kernel<<<1, 256>>>();

    const int total_thr = B * C * (L / 8);      // 131072
    lif_kernel<<<total_thr / 256, 256>>>(in, enc_w, enc_b, bn_gamma, bn_beta, out);
}